// round 4
// baseline (speedup 1.0000x reference)
#include <cuda_runtime.h>
#include <math.h>
#include <stdint.h>

#define TT 32
#define NN 256
#define LL 512
#define HH 128
#define G3 384
#define NA 16
#define TOTP 277
#define WS 132

__device__ float g_X[LL*NN*HH];     // conv out / layer outputs (64MB)
__device__ float g_gi[LL*NN*G3];    // precomputed input-gates (201MB)
__device__ float g_G[TT*NN*HH];     // gathered memory rows
__device__ float g_gum[TT*NN*NA];   // gumbel noise

// ---------------------------------------------------------------- conv
__global__ void conv_k(const float* __restrict__ obs, const float* __restrict__ cw,
                       const float* __restrict__ cb) {
    int l = blockIdx.x, n = blockIdx.y, h = threadIdx.x;
    __shared__ float xs[9];
    if (h < 9) { int p = l - 4 + h; xs[h] = (p >= 0 && p < LL) ? obs[n*LL + p] : 0.f; }
    __syncthreads();
    float acc = cb[h];
#pragma unroll
    for (int k = 0; k < 9; k++) acc = fmaf(xs[k], cw[h*9 + k], acc);
    g_X[(l*NN + n)*HH + h] = fmaxf(acc, 0.f);
}

// ------------------------------------------------ GEMM: C[r][g] = bias[g] + X[r]·W[g]
// X [R,128] row-major, W [384,128] row-major, C [R,384]. Tile 64x64, 256 thr.
__global__ void gemm_k(const float* __restrict__ X, const float* __restrict__ W,
                       const float* __restrict__ bias, float* __restrict__ C) {
    extern __shared__ float sm[];
    float* Xs = sm;            // [128][65] k-major
    float* Wsm = sm + 128*65;  // [128][65]
    int tid = threadIdx.x, tx = tid & 15, ty = tid >> 4;
    int r0 = blockIdx.x * 64, g0 = blockIdx.y * 64;
    {
        int kk = (tid & 31) * 4, rr = tid >> 5;
#pragma unroll
        for (int p = 0; p < 8; p++) {
            int r = rr + p * 8;
            float4 v = *(const float4*)&X[(size_t)(r0 + r) * HH + kk];
            Xs[(kk+0)*65 + r] = v.x; Xs[(kk+1)*65 + r] = v.y;
            Xs[(kk+2)*65 + r] = v.z; Xs[(kk+3)*65 + r] = v.w;
            float4 w = *(const float4*)&W[(size_t)(g0 + r) * HH + kk];
            Wsm[(kk+0)*65 + r] = w.x; Wsm[(kk+1)*65 + r] = w.y;
            Wsm[(kk+2)*65 + r] = w.z; Wsm[(kk+3)*65 + r] = w.w;
        }
    }
    __syncthreads();
    float c[4][4] = {};
#pragma unroll 8
    for (int k = 0; k < 128; k++) {
        float a0 = Xs[k*65 + ty],      a1 = Xs[k*65 + ty + 16];
        float a2 = Xs[k*65 + ty + 32], a3 = Xs[k*65 + ty + 48];
        float b0 = Wsm[k*65 + tx],      b1 = Wsm[k*65 + tx + 16];
        float b2 = Wsm[k*65 + tx + 32], b3 = Wsm[k*65 + tx + 48];
        c[0][0]=fmaf(a0,b0,c[0][0]); c[0][1]=fmaf(a0,b1,c[0][1]);
        c[0][2]=fmaf(a0,b2,c[0][2]); c[0][3]=fmaf(a0,b3,c[0][3]);
        c[1][0]=fmaf(a1,b0,c[1][0]); c[1][1]=fmaf(a1,b1,c[1][1]);
        c[1][2]=fmaf(a1,b2,c[1][2]); c[1][3]=fmaf(a1,b3,c[1][3]);
        c[2][0]=fmaf(a2,b0,c[2][0]); c[2][1]=fmaf(a2,b1,c[2][1]);
        c[2][2]=fmaf(a2,b2,c[2][2]); c[2][3]=fmaf(a2,b3,c[2][3]);
        c[3][0]=fmaf(a3,b0,c[3][0]); c[3][1]=fmaf(a3,b1,c[3][1]);
        c[3][2]=fmaf(a3,b2,c[3][2]); c[3][3]=fmaf(a3,b3,c[3][3]);
    }
#pragma unroll
    for (int i = 0; i < 4; i++) {
        int r = r0 + ty + 16 * i;
#pragma unroll
        for (int j = 0; j < 4; j++) {
            int g = g0 + tx + 16 * j;
            C[(size_t)r * G3 + g] = c[i][j] + bias[g];
        }
    }
}

// ---------------------------------------------- GRU recurrence (zero init), one layer
// 128 CTAs x 2 samples, 384 threads; W_hh in smem; gi precomputed (incl. bih).
__global__ void __launch_bounds__(384, 1)
recur_k(const float* __restrict__ gi, const float* __restrict__ whh,
        const float* __restrict__ bhh, float* __restrict__ out, int steps) {
    extern __shared__ float sm[];
    float* Wsm = sm;             // 384*132
    float* h_s = Wsm + G3 * WS;  // 2*128
    float* su  = h_s + 2 * HH;   // 2*384
    float* gin = su + 2 * G3;    // 2*128
    int g = threadIdx.x;
    int n0 = blockIdx.x * 2, n1 = n0 + 1;
#pragma unroll
    for (int k = 0; k < HH; k += 4)
        *(float4*)&Wsm[g * WS + k] = *(const float4*)&whh[g * HH + k];
    float bv = bhh[g];
    if (g < 2 * HH) h_s[g] = 0.f;
    __syncthreads();
    for (int t = 0; t < steps; t++) {
        const float* gp = gi + (size_t)t * NN * G3;
        float gia = gp[n0 * G3 + g];
        float gib = gp[n1 * G3 + g];
        float a0 = bv, a1 = bv;
        const float* wr = &Wsm[g * WS];
#pragma unroll
        for (int k = 0; k < HH; k += 4) {
            float4 w = *(const float4*)&wr[k];
            float4 p = *(const float4*)&h_s[k];
            float4 q = *(const float4*)&h_s[HH + k];
            a0 = fmaf(w.x, p.x, a0); a0 = fmaf(w.y, p.y, a0);
            a0 = fmaf(w.z, p.z, a0); a0 = fmaf(w.w, p.w, a0);
            a1 = fmaf(w.x, q.x, a1); a1 = fmaf(w.y, q.y, a1);
            a1 = fmaf(w.z, q.z, a1); a1 = fmaf(w.w, q.w, a1);
        }
        if (g < 256) { su[g] = gia + a0; su[G3 + g] = gib + a1; }
        else { su[g] = a0; su[G3 + g] = a1; gin[g - 256] = gia; gin[HH + g - 256] = gib; }
        __syncthreads();
        if (g < 2 * HH) {
            int s = g >> 7, j = g & 127;
            const float* ss = su + s * G3;
            float r = 1.f / (1.f + __expf(-ss[j]));
            float z = 1.f / (1.f + __expf(-ss[128 + j]));
            float nn = tanhf(fmaf(r, ss[256 + j], gin[s * HH + j]));
            float hn = (1.f - z) * nn + z * h_s[g];
            h_s[g] = hn;
            int n = n0 + s;
            out[((size_t)t * NN + n) * HH + j] = hn;
        }
        __syncthreads();
    }
}

// ---------------------------------------------------------------- gather M[n, p0+t]
__global__ void gather_k(const int* __restrict__ p0) {
    int t = blockIdx.x, n = blockIdx.y, h = threadIdx.x;
    int p = p0[n] + t;
    g_G[((size_t)t * NN + n) * HH + h] = g_X[((size_t)p * NN + n) * HH + h];
}

// ---------------------------------------------------------------- threefry gumbel
// JAX >= 0.4.30 default: threefry_partitionable=True.
// bits[i] = o0 ^ o1 where (o0,o1) = threefry2x32(key, (hi32(i)=0, lo32(i)=i)).
__device__ __forceinline__ uint32_t rotl32(uint32_t x, int r) { return (x << r) | (x >> (32 - r)); }
__device__ __forceinline__ float bits_to_gumbel(uint32_t b) {
    uint32_t fb = (b >> 9) | 0x3f800000u;
    float f = __uint_as_float(fb) - 1.0f;
    float u = (f > 0.f) ? f : 1.17549435e-38f;
    return -logf(-logf(u));
}
__global__ void gumbel_k() {
    int i = blockIdx.x * blockDim.x + threadIdx.x;
    if (i >= TT*NN*NA) return;
    const uint32_t ks0 = 0u, ks1 = 42u, ks2 = ks0 ^ ks1 ^ 0x1BD11BDAu;
    uint32_t x0 = 0u + ks0, x1 = (uint32_t)i + ks1;
#define RG4(a,b,c,d) \
    x0 += x1; x1 = rotl32(x1,a); x1 ^= x0; \
    x0 += x1; x1 = rotl32(x1,b); x1 ^= x0; \
    x0 += x1; x1 = rotl32(x1,c); x1 ^= x0; \
    x0 += x1; x1 = rotl32(x1,d); x1 ^= x0;
    RG4(13,15,26,6)  x0 += ks1; x1 += ks2 + 1u;
    RG4(17,29,16,24) x0 += ks2; x1 += ks0 + 2u;
    RG4(13,15,26,6)  x0 += ks0; x1 += ks1 + 3u;
    RG4(17,29,16,24) x0 += ks1; x1 += ks2 + 4u;
    RG4(13,15,26,6)  x0 += ks2; x1 += ks0 + 5u;
#undef RG4
    g_gum[i] = bits_to_gumbel(x0 ^ x1);
}

// ---------------------------------------------------------------- phase 3: T-step GRU + heads
__global__ void __launch_bounds__(384, 1)
phase3_k(const float* __restrict__ gi0,
         const float* __restrict__ bhh0, const float* __restrict__ wih1,
         const float* __restrict__ bih1, const float* __restrict__ whh1,
         const float* __restrict__ bhh1, const float* __restrict__ h0in,
         const int* __restrict__ actions, const int* __restrict__ p0,
         const float* __restrict__ loc, const float* __restrict__ scale,
         const float* __restrict__ crw, const float* __restrict__ crb,
         const float* __restrict__ aw, const float* __restrict__ ab,
         const float* __restrict__ whh0,
         float* __restrict__ out, int has_tail) {
    extern __shared__ float sm[];
    float* Wsm = sm;              // 384*132 (whh layer0)
    float* h0s = Wsm + G3 * WS;   // 2*128
    float* h1s = h0s + 2 * HH;    // 2*128
    float* su  = h1s + 2 * HH;    // 2*384
    float* gin = su + 2 * G3;     // 2*128
    float* hd  = gin + 2 * HH;    // 34
    int g = threadIdx.x;
    int n0 = blockIdx.x * 2, n1 = n0 + 1;
#pragma unroll
    for (int k = 0; k < HH; k += 4)
        *(float4*)&Wsm[g * WS + k] = *(const float4*)&whh0[g * HH + k];
    float bh0 = bhh0[g], bi1 = bih1[g], bh1 = bhh1[g];
    if (g < 2 * HH) {
        int s = g >> 7, j = g & 127, n = n0 + s;
        h0s[g] = h0in[(size_t)n * HH + j];
        h1s[g] = h0in[(size_t)(NN + n) * HH + j];
    }
    __syncthreads();
    for (int t = 0; t < TT; t++) {
        // ----- layer 0 -----
        const float* gp = gi0 + (size_t)t * NN * G3;
        float gia = gp[n0 * G3 + g];
        float gib = gp[n1 * G3 + g];
        float a0 = bh0, a1 = bh0;
        const float* wr = &Wsm[g * WS];
#pragma unroll
        for (int k = 0; k < HH; k += 4) {
            float4 w = *(const float4*)&wr[k];
            float4 p = *(const float4*)&h0s[k];
            float4 q = *(const float4*)&h0s[HH + k];
            a0 = fmaf(w.x, p.x, a0); a0 = fmaf(w.y, p.y, a0);
            a0 = fmaf(w.z, p.z, a0); a0 = fmaf(w.w, p.w, a0);
            a1 = fmaf(w.x, q.x, a1); a1 = fmaf(w.y, q.y, a1);
            a1 = fmaf(w.z, q.z, a1); a1 = fmaf(w.w, q.w, a1);
        }
        if (g < 256) { su[g] = gia + a0; su[G3 + g] = gib + a1; }
        else { su[g] = a0; su[G3 + g] = a1; gin[g - 256] = gia; gin[HH + g - 256] = gib; }
        __syncthreads();
        if (g < 2 * HH) {
            int s = g >> 7, j = g & 127;
            const float* ss = su + s * G3;
            float r = 1.f / (1.f + __expf(-ss[j]));
            float z = 1.f / (1.f + __expf(-ss[128 + j]));
            float nn = tanhf(fmaf(r, ss[256 + j], gin[s * HH + j]));
            h0s[g] = (1.f - z) * nn + z * h0s[g];
        }
        __syncthreads();
        // ----- layer 1 -----
        float b0 = bi1, b1 = bi1, c0 = bh1, c1 = bh1;
        const float4* wi4 = (const float4*)&wih1[(size_t)g * HH];
        const float4* wh4 = (const float4*)&whh1[(size_t)g * HH];
#pragma unroll
        for (int k4 = 0; k4 < 32; k4++) {
            float4 wi = wi4[k4], wh = wh4[k4];
            float4 x0 = *(const float4*)&h0s[k4 * 4];
            float4 x1 = *(const float4*)&h0s[HH + k4 * 4];
            float4 y0 = *(const float4*)&h1s[k4 * 4];
            float4 y1 = *(const float4*)&h1s[HH + k4 * 4];
            b0 = fmaf(wi.x, x0.x, b0); b0 = fmaf(wi.y, x0.y, b0);
            b0 = fmaf(wi.z, x0.z, b0); b0 = fmaf(wi.w, x0.w, b0);
            b1 = fmaf(wi.x, x1.x, b1); b1 = fmaf(wi.y, x1.y, b1);
            b1 = fmaf(wi.z, x1.z, b1); b1 = fmaf(wi.w, x1.w, b1);
            c0 = fmaf(wh.x, y0.x, c0); c0 = fmaf(wh.y, y0.y, c0);
            c0 = fmaf(wh.z, y0.z, c0); c0 = fmaf(wh.w, y0.w, c0);
            c1 = fmaf(wh.x, y1.x, c1); c1 = fmaf(wh.y, y1.y, c1);
            c1 = fmaf(wh.z, y1.z, c1); c1 = fmaf(wh.w, y1.w, c1);
        }
        if (g < 256) { su[g] = b0 + c0; su[G3 + g] = b1 + c1; }
        else { su[g] = c0; su[G3 + g] = c1; gin[g - 256] = b0; gin[HH + g - 256] = b1; }
        __syncthreads();
        if (g < 2 * HH) {
            int s = g >> 7, j = g & 127;
            const float* ss = su + s * G3;
            float r = 1.f / (1.f + __expf(-ss[j]));
            float z = 1.f / (1.f + __expf(-ss[128 + j]));
            float nn = tanhf(fmaf(r, ss[256 + j], gin[s * HH + j]));
            h1s[g] = (1.f - z) * nn + z * h1s[g];
        }
        __syncthreads();
        // ----- heads: 17 dots per sample -----
        if (g < 34) {
            int s = g / 17, idx = g % 17;
            const float* w = (idx == 0) ? crw : (aw + (size_t)(idx - 1) * HH);
            float bb = (idx == 0) ? crb[0] : ab[idx - 1];
            const float* hv = h1s + s * HH;
            float d0 = 0.f, d1 = 0.f, d2 = 0.f, d3 = 0.f;
#pragma unroll
            for (int k = 0; k < HH; k += 4) {
                d0 = fmaf(w[k], hv[k], d0);     d1 = fmaf(w[k+1], hv[k+1], d1);
                d2 = fmaf(w[k+2], hv[k+2], d2); d3 = fmaf(w[k+3], hv[k+3], d3);
            }
            hd[g] = bb + ((d0 + d1) + (d2 + d3));
        }
        __syncthreads();
        // ----- pack output row -----
        if (g < 2) {
            int s = g, n = n0 + s;
            float* row = out + ((size_t)t * NN + n) * TOTP;
            const float* lg = hd + s * 17 + 1;
            float m = lg[0];
#pragma unroll
            for (int a = 1; a < NA; a++) m = fmaxf(m, lg[a]);
            float ex[NA]; float es = 0.f;
#pragma unroll
            for (int a = 0; a < NA; a++) { ex[a] = expf(lg[a] - m); es += ex[a]; }
            float inv = 1.f / es;
            const float* gm = g_gum + ((size_t)t * NN + n) * NA;
            int best = 0; float bvv = lg[0] + gm[0];
#pragma unroll
            for (int a = 1; a < NA; a++) {
                float vv = lg[a] + gm[a];
                if (vv > bvv) { bvv = vv; best = a; }
            }
            int at = actions[t * NN + n];
            int aa = (at < 0) ? best : at;
            row[0] = (float)aa;
#pragma unroll
            for (int a = 0; a < NA; a++) row[1 + a] = ex[a] * inv;
            row[17] = loc[n]; row[18] = scale[n]; row[19] = hd[s * 17];
            row[276] = (float)(p0[n] + t + 1);
            if (has_tail && t == TT - 1) {
                float* r2 = out + ((size_t)TT * NN + n) * TOTP;
                for (int q = 0; q < 20; q++) r2[q] = row[q];
                r2[276] = row[276];
            }
        }
        if (g < 2 * HH) {
            int s = g >> 7, j = g & 127, n = n0 + s;
            float* row = out + ((size_t)t * NN + n) * TOTP;
            row[20 + j] = h0s[g];
            row[148 + j] = h1s[g];
            if (has_tail && t == TT - 1) {
                float* r2 = out + ((size_t)TT * NN + n) * TOTP;
                r2[20 + j] = h0s[g];
                r2[148 + j] = h1s[g];
            }
        }
        __syncthreads();
    }
}

// ---------------------------------------------------------------- launch
extern "C" void kernel_launch(void* const* d_in, const int* in_sizes, int n_in,
                              void* d_out, int out_size) {
    const float* obs    = (const float*)d_in[0];
    const int*   acts   = (const int*)d_in[1];
    const int*   p0     = (const int*)d_in[2];
    const float* h0     = (const float*)d_in[3];
    const float* loc    = (const float*)d_in[4];
    const float* scl    = (const float*)d_in[5];
    const float* conv_w = (const float*)d_in[6];
    const float* conv_b = (const float*)d_in[7];
    const float* g0wih  = (const float*)d_in[8];
    const float* g0whh  = (const float*)d_in[9];
    const float* g0bih  = (const float*)d_in[10];
    const float* g0bhh  = (const float*)d_in[11];
    const float* g1wih  = (const float*)d_in[12];
    const float* g1whh  = (const float*)d_in[13];
    const float* g1bih  = (const float*)d_in[14];
    const float* g1bhh  = (const float*)d_in[15];
    const float* crw    = (const float*)d_in[16];
    const float* crb    = (const float*)d_in[17];
    const float* aw     = (const float*)d_in[18];
    const float* ab     = (const float*)d_in[19];
    float* out = (float*)d_out;

    float *pX, *pGi, *pG;
    cudaGetSymbolAddress((void**)&pX, g_X);
    cudaGetSymbolAddress((void**)&pGi, g_gi);
    cudaGetSymbolAddress((void**)&pG, g_G);

    const int GEMM_SMEM = 2 * 128 * 65 * 4;                        // 66,560 B
    const int REC_SMEM  = (G3*WS + 2*HH + 2*G3 + 2*HH) * 4;        // 207,872 B
    const int P3_SMEM   = (G3*WS + 4*HH + 2*G3 + 2*HH + 34) * 4;   // 210,048 B
    cudaFuncSetAttribute(gemm_k, cudaFuncAttributeMaxDynamicSharedMemorySize, GEMM_SMEM);
    cudaFuncSetAttribute(recur_k, cudaFuncAttributeMaxDynamicSharedMemorySize, REC_SMEM);
    cudaFuncSetAttribute(phase3_k, cudaFuncAttributeMaxDynamicSharedMemorySize, P3_SMEM);

    int has_tail = (out_size >= TT*NN*TOTP + NN*TOTP) ? 1 : 0;

    // phase 1: conv
    conv_k<<<dim3(LL, NN), HH>>>(obs, conv_w, conv_b);
    // phase 2: gru0 layer 0
    gemm_k<<<dim3(LL*NN/64, G3/64), 256, GEMM_SMEM>>>(pX, g0wih, g0bih, pGi);
    recur_k<<<NN/2, 384, REC_SMEM>>>(pGi, g0whh, g0bhh, pX, LL);
    // phase 2: gru0 layer 1
    gemm_k<<<dim3(LL*NN/64, G3/64), 256, GEMM_SMEM>>>(pX, g0wih + G3*HH, g0bih + G3, pGi);
    recur_k<<<NN/2, 384, REC_SMEM>>>(pGi, g0whh + G3*HH, g0bhh + G3, pX, LL);
    // phase 3 prep
    gather_k<<<dim3(TT, NN), HH>>>(p0);
    gemm_k<<<dim3(TT*NN/64, G3/64), 256, GEMM_SMEM>>>(pG, g1wih, g1bih, pGi);
    gumbel_k<<<512, 256>>>();
    // phase 3
    phase3_k<<<NN/2, 384, P3_SMEM>>>(pGi, g1bhh, g1wih + G3*HH, g1bih + G3,
                                     g1whh + G3*HH, g1bhh + G3, h0,
                                     acts, p0, loc, scl, crw, crb, aw, ab,
                                     g1whh, out, has_tail);
}

// round 5
// speedup vs baseline: 1.4974x; 1.4974x over previous
#include <cuda_runtime.h>
#include <math.h>
#include <stdint.h>

#define TT 32
#define NN 256
#define LL 512
#define HH 128
#define G3 384
#define NA 16
#define TOTP 277
#define XP 130   // float2 pitch for duplicated X tile
#define WP 132   // float pitch for W tile

typedef unsigned long long u64;

__device__ __forceinline__ u64 ff2(u64 a, u64 b, u64 c) {
    u64 d;
    asm("fma.rn.f32x2 %0, %1, %2, %3;" : "=l"(d) : "l"(a), "l"(b), "l"(c));
    return d;
}
__device__ __forceinline__ float2 unpack(u64 v) {
    float2 r;
    asm("mov.b64 {%0,%1}, %2;" : "=f"(r.x), "=f"(r.y) : "l"(v));
    return r;
}

__device__ float g_X[LL*NN*HH];     // conv out / layer outputs
__device__ float g_gi[LL*NN*G3];    // precomputed input-gates
__device__ float g_G[TT*NN*HH];     // gathered rows, then H0 series
__device__ float g_H1[TT*NN*HH];    // H1 series
__device__ float g_gum[TT*NN*NA];   // gumbel noise

// ---------------------------------------------------------------- conv
__global__ void conv_k(const float* __restrict__ obs, const float* __restrict__ cw,
                       const float* __restrict__ cb) {
    int l = blockIdx.x, n = blockIdx.y, h = threadIdx.x;
    __shared__ float xs[9];
    if (h < 9) { int p = l - 4 + h; xs[h] = (p >= 0 && p < LL) ? obs[n*LL + p] : 0.f; }
    __syncthreads();
    float acc = cb[h];
#pragma unroll
    for (int k = 0; k < 9; k++) acc = fmaf(xs[k], cw[h*9 + k], acc);
    g_X[(l*NN + n)*HH + h] = fmaxf(acc, 0.f);
}

// ------------------------------------------------ GEMM: C[r][g] = bias[g] + X[r]·W[g]
// X [R,128] row-major, W [384,128] row-major, C [R,384]. 128x128 tile, 256 thr,
// 8x8 micro-tile, f32x2 packed FMA with duplicated-X smem tile (no pack MOVs).
__global__ void __launch_bounds__(256, 1)
gemm2_k(const float* __restrict__ X, const float* __restrict__ W,
        const float* __restrict__ bias, float* __restrict__ C, int R) {
    extern __shared__ float sm[];
    float2* Xs = (float2*)sm;              // [128][XP] duplicated (x,x)
    float*  Ws = sm + 2*128*XP;            // [128][WP]
    int tid = threadIdx.x;
    int r0 = blockIdx.x * 128, g0 = blockIdx.y * 128;
    // X tile: coalesced float4 global loads, transposed dup stores
#pragma unroll
    for (int it = 0; it < 16; it++) {
        int idx = it * 256 + tid;
        int r = idx >> 5, kq = (idx & 31) * 4;
        float4 v = *(const float4*)&X[(size_t)(r0 + r) * HH + kq];
        Xs[(kq+0)*XP + r] = make_float2(v.x, v.x);
        Xs[(kq+1)*XP + r] = make_float2(v.y, v.y);
        Xs[(kq+2)*XP + r] = make_float2(v.z, v.z);
        Xs[(kq+3)*XP + r] = make_float2(v.w, v.w);
    }
    // W tile: lane = gate col (conflict-free stores); W is L2-hot
#pragma unroll
    for (int it = 0; it < 16; it++) {
        int idx = it * 256 + tid;
        int g = idx & 127, kq = (idx >> 7) * 4;
        float4 w = *(const float4*)&W[(size_t)(g0 + g) * HH + kq];
        Ws[(kq+0)*WP + g] = w.x;
        Ws[(kq+1)*WP + g] = w.y;
        Ws[(kq+2)*WP + g] = w.z;
        Ws[(kq+3)*WP + g] = w.w;
    }
    __syncthreads();
    int tx = tid & 15, ty = tid >> 4;
    u64 acc[8][4];
#pragma unroll
    for (int i = 0; i < 8; i++)
#pragma unroll
        for (int j = 0; j < 4; j++) acc[i][j] = 0ULL;
#pragma unroll 4
    for (int k = 0; k < 128; k++) {
        const float2* xk = Xs + k * XP;
        const float*  wk = Ws + k * WP;
        ulonglong2 a01 = *(const ulonglong2*)(xk + ty*4);
        ulonglong2 a23 = *(const ulonglong2*)(xk + ty*4 + 2);
        ulonglong2 a45 = *(const ulonglong2*)(xk + ty*4 + 64);
        ulonglong2 a67 = *(const ulonglong2*)(xk + ty*4 + 66);
        ulonglong2 b03 = *(const ulonglong2*)(wk + tx*4);
        ulonglong2 b47 = *(const ulonglong2*)(wk + tx*4 + 64);
        u64 av[8] = {a01.x, a01.y, a23.x, a23.y, a45.x, a45.y, a67.x, a67.y};
        u64 bv[4] = {b03.x, b03.y, b47.x, b47.y};
#pragma unroll
        for (int i = 0; i < 8; i++)
#pragma unroll
            for (int j = 0; j < 4; j++)
                acc[i][j] = ff2(av[i], bv[j], acc[i][j]);
    }
    float4 bA = *(const float4*)&bias[g0 + tx*4];
    float4 bB = *(const float4*)&bias[g0 + tx*4 + 64];
#pragma unroll
    for (int i = 0; i < 8; i++) {
        int r = r0 + ty*4 + (i & 3) + (i >> 2) * 64;
        float2 q0 = unpack(acc[i][0]), q1 = unpack(acc[i][1]);
        float2 q2 = unpack(acc[i][2]), q3 = unpack(acc[i][3]);
        float4 o0 = make_float4(q0.x + bA.x, q0.y + bA.y, q1.x + bA.z, q1.y + bA.w);
        float4 o1 = make_float4(q2.x + bB.x, q2.y + bB.y, q3.x + bB.z, q3.y + bB.w);
        *(float4*)&C[(size_t)r * G3 + g0 + tx*4]      = o0;
        *(float4*)&C[(size_t)r * G3 + g0 + tx*4 + 64] = o1;
    }
}

// ---------------------------------------------- GRU recurrence, one layer
// 128 CTAs x 2 samples, 384 threads. W_hh k=0..95 in registers (48 u64 pairs),
// k=96..127 in smem. k-paired f32x2 FMA. gi precomputed (incl. bih).
__global__ void __launch_bounds__(384, 1)
recur2_k(const float* __restrict__ gi, const float* __restrict__ whh,
         const float* __restrict__ bhh, const float* __restrict__ h0i,
         float* __restrict__ out, int steps) {
    extern __shared__ float sm[];
    float* Wsm = sm;                 // [384][36] k=96..127 (pitch 36, conflict-free)
    float* h_s = Wsm + 384*36;       // [2][128]
    float* su  = h_s + 256;          // [2][384]
    float* gin = su + 768;           // [2][128]
    int g = threadIdx.x;
    int n0 = blockIdx.x * 2;
    u64 wr[48];
#pragma unroll
    for (int i = 0; i < 24; i++) {
        ulonglong2 t = *(const ulonglong2*)&whh[(size_t)g * HH + 4*i];
        wr[2*i] = t.x; wr[2*i+1] = t.y;
    }
#pragma unroll
    for (int j = 0; j < 8; j++)
        *(float4*)&Wsm[g*36 + 4*j] = *(const float4*)&whh[(size_t)g * HH + 96 + 4*j];
    float bv = bhh[g];
    if (g < 256) {
        int s = g >> 7, j = g & 127;
        h_s[g] = h0i ? h0i[(size_t)(n0 + s) * HH + j] : 0.f;
    }
    __syncthreads();
    const ulonglong2* h0p = (const ulonglong2*)h_s;
    const ulonglong2* h1p = (const ulonglong2*)(h_s + HH);
    const ulonglong2* wsp = (const ulonglong2*)&Wsm[g*36];
    for (int t = 0; t < steps; t++) {
        const float* gp = gi + (size_t)t * NN * G3;
        float gia = gp[n0 * G3 + g];
        float gib = gp[(n0 + 1) * G3 + g];
        u64 a0a = 0, a0b = 0, a1a = 0, a1b = 0;
#pragma unroll
        for (int i = 0; i < 24; i++) {
            ulonglong2 ha = h0p[i], hb = h1p[i];
            a0a = ff2(wr[2*i],   ha.x, a0a);
            a0b = ff2(wr[2*i+1], ha.y, a0b);
            a1a = ff2(wr[2*i],   hb.x, a1a);
            a1b = ff2(wr[2*i+1], hb.y, a1b);
        }
#pragma unroll
        for (int i = 0; i < 8; i++) {
            ulonglong2 ww = wsp[i];
            ulonglong2 ha = h0p[24+i], hb = h1p[24+i];
            a0a = ff2(ww.x, ha.x, a0a);
            a0b = ff2(ww.y, ha.y, a0b);
            a1a = ff2(ww.x, hb.x, a1a);
            a1b = ff2(ww.y, hb.y, a1b);
        }
        float2 s0a = unpack(a0a), s0b = unpack(a0b);
        float2 s1a = unpack(a1a), s1b = unpack(a1b);
        float a0 = bv + ((s0a.x + s0a.y) + (s0b.x + s0b.y));
        float a1 = bv + ((s1a.x + s1a.y) + (s1b.x + s1b.y));
        if (g < 256) { su[g] = gia + a0; su[G3 + g] = gib + a1; }
        else { su[g] = a0; su[G3 + g] = a1; gin[g - 256] = gia; gin[HH + g - 256] = gib; }
        __syncthreads();
        if (g < 256) {
            int s = g >> 7, j = g & 127;
            const float* ss = su + s * G3;
            float r = 1.f / (1.f + __expf(-ss[j]));
            float z = 1.f / (1.f + __expf(-ss[128 + j]));
            float y = fmaf(r, ss[256 + j], gin[s * HH + j]);
            float e = __expf(-2.f * fabsf(y));
            float th = (1.f - e) / (1.f + e);
            th = (y < 0.f) ? -th : th;
            float hn = (1.f - z) * th + z * h_s[g];
            h_s[g] = hn;
            out[((size_t)t * NN + n0 + s) * HH + j] = hn;
        }
        __syncthreads();
    }
}

// ---------------------------------------------------------------- gather M[n, p0+t]
__global__ void gather_k(const int* __restrict__ p0) {
    int t = blockIdx.x, n = blockIdx.y, h = threadIdx.x;
    int p = p0[n] + t;
    g_G[((size_t)t * NN + n) * HH + h] = g_X[((size_t)p * NN + n) * HH + h];
}

// ---------------------------------------------------------------- threefry gumbel
// JAX partitionable threefry: bits[i] = o0 ^ o1, counter (0, i), key (0, 42).
__device__ __forceinline__ uint32_t rotl32(uint32_t x, int r) { return (x << r) | (x >> (32 - r)); }
__device__ __forceinline__ float bits_to_gumbel(uint32_t b) {
    uint32_t fb = (b >> 9) | 0x3f800000u;
    float f = __uint_as_float(fb) - 1.0f;
    float u = (f > 0.f) ? f : 1.17549435e-38f;
    return -logf(-logf(u));
}
__global__ void gumbel_k() {
    int i = blockIdx.x * blockDim.x + threadIdx.x;
    if (i >= TT*NN*NA) return;
    const uint32_t ks0 = 0u, ks1 = 42u, ks2 = ks0 ^ ks1 ^ 0x1BD11BDAu;
    uint32_t x0 = 0u + ks0, x1 = (uint32_t)i + ks1;
#define RG4(a,b,c,d) \
    x0 += x1; x1 = rotl32(x1,a); x1 ^= x0; \
    x0 += x1; x1 = rotl32(x1,b); x1 ^= x0; \
    x0 += x1; x1 = rotl32(x1,c); x1 ^= x0; \
    x0 += x1; x1 = rotl32(x1,d); x1 ^= x0;
    RG4(13,15,26,6)  x0 += ks1; x1 += ks2 + 1u;
    RG4(17,29,16,24) x0 += ks2; x1 += ks0 + 2u;
    RG4(13,15,26,6)  x0 += ks0; x1 += ks1 + 3u;
    RG4(17,29,16,24) x0 += ks1; x1 += ks2 + 4u;
    RG4(13,15,26,6)  x0 += ks2; x1 += ks0 + 5u;
#undef RG4
    g_gum[i] = bits_to_gumbel(x0 ^ x1);
}

// ---------------------------------------------------------------- heads + pack
__global__ void __launch_bounds__(64)
pack_k(const float* __restrict__ H0, const float* __restrict__ H1,
       const int* __restrict__ actions, const int* __restrict__ p0,
       const float* __restrict__ loc, const float* __restrict__ scale,
       const float* __restrict__ crw, const float* __restrict__ crb,
       const float* __restrict__ aw, const float* __restrict__ ab,
       float* __restrict__ out, int has_tail) {
    int bx = blockIdx.x;
    int t = bx >> 8, n = bx & 255;
    int tid = threadIdx.x;
    __shared__ float h1s[128];
    __shared__ float hd[17];
    const float* h1g = H1 + ((size_t)t * NN + n) * HH;
    h1s[tid] = h1g[tid]; h1s[tid + 64] = h1g[tid + 64];
    __syncthreads();
    if (tid < 17) {
        const float* w = (tid == 0) ? crw : (aw + (size_t)(tid - 1) * HH);
        float b = (tid == 0) ? crb[0] : ab[tid - 1];
        float d0 = 0, d1 = 0, d2 = 0, d3 = 0;
#pragma unroll
        for (int k = 0; k < HH; k += 4) {
            d0 = fmaf(w[k],   h1s[k],   d0); d1 = fmaf(w[k+1], h1s[k+1], d1);
            d2 = fmaf(w[k+2], h1s[k+2], d2); d3 = fmaf(w[k+3], h1s[k+3], d3);
        }
        hd[tid] = b + ((d0 + d1) + (d2 + d3));
    }
    __syncthreads();
    float* row  = out + ((size_t)t * NN + n) * TOTP;
    float* row2 = out + ((size_t)TT * NN + n) * TOTP;
    bool tail = has_tail && (t == TT - 1);
    if (tid == 0) {
        const float* lg = hd + 1;
        float m = lg[0];
#pragma unroll
        for (int a = 1; a < NA; a++) m = fmaxf(m, lg[a]);
        float ex[NA], es = 0.f;
#pragma unroll
        for (int a = 0; a < NA; a++) { ex[a] = expf(lg[a] - m); es += ex[a]; }
        float inv = 1.f / es;
        const float* gm = g_gum + ((size_t)t * NN + n) * NA;
        int best = 0; float bb = lg[0] + gm[0];
#pragma unroll
        for (int a = 1; a < NA; a++) {
            float v = lg[a] + gm[a];
            if (v > bb) { bb = v; best = a; }
        }
        int at = actions[t * NN + n];
        float av = (float)((at < 0) ? best : at);
        row[0] = av;
#pragma unroll
        for (int a = 0; a < NA; a++) row[1 + a] = ex[a] * inv;
        row[17] = loc[n]; row[18] = scale[n]; row[19] = hd[0];
        row[276] = (float)(p0[n] + t + 1);
        if (tail) {
            row2[0] = av;
            for (int a = 0; a < NA; a++) row2[1 + a] = ex[a] * inv;
            row2[17] = loc[n]; row2[18] = scale[n]; row2[19] = hd[0];
            row2[276] = row[276];
        }
    }
    const float* h0g = H0 + ((size_t)t * NN + n) * HH;
#pragma unroll
    for (int q = 0; q < 2; q++) {
        int j = tid + q * 64;
        float v0 = h0g[j], v1 = h1s[j];
        row[20 + j] = v0; row[148 + j] = v1;
        if (tail) { row2[20 + j] = v0; row2[148 + j] = v1; }
    }
}

// ---------------------------------------------------------------- launch
extern "C" void kernel_launch(void* const* d_in, const int* in_sizes, int n_in,
                              void* d_out, int out_size) {
    const float* obs    = (const float*)d_in[0];
    const int*   acts   = (const int*)d_in[1];
    const int*   p0     = (const int*)d_in[2];
    const float* h0     = (const float*)d_in[3];
    const float* loc    = (const float*)d_in[4];
    const float* scl    = (const float*)d_in[5];
    const float* conv_w = (const float*)d_in[6];
    const float* conv_b = (const float*)d_in[7];
    const float* g0wih  = (const float*)d_in[8];
    const float* g0whh  = (const float*)d_in[9];
    const float* g0bih  = (const float*)d_in[10];
    const float* g0bhh  = (const float*)d_in[11];
    const float* g1wih  = (const float*)d_in[12];
    const float* g1whh  = (const float*)d_in[13];
    const float* g1bih  = (const float*)d_in[14];
    const float* g1bhh  = (const float*)d_in[15];
    const float* crw    = (const float*)d_in[16];
    const float* crb    = (const float*)d_in[17];
    const float* aw     = (const float*)d_in[18];
    const float* ab     = (const float*)d_in[19];
    float* out = (float*)d_out;

    float *pX, *pGi, *pG, *pH1;
    cudaGetSymbolAddress((void**)&pX, g_X);
    cudaGetSymbolAddress((void**)&pGi, g_gi);
    cudaGetSymbolAddress((void**)&pG, g_G);
    cudaGetSymbolAddress((void**)&pH1, g_H1);

    const int GEMM_SMEM = (2*128*XP + 128*WP) * 4;          // 200,704 B
    const int REC_SMEM  = (384*36 + 256 + 768 + 256) * 4;   // 60,416 B
    cudaFuncSetAttribute(gemm2_k, cudaFuncAttributeMaxDynamicSharedMemorySize, GEMM_SMEM);
    cudaFuncSetAttribute(recur2_k, cudaFuncAttributeMaxDynamicSharedMemorySize, REC_SMEM);

    int has_tail = (out_size >= TT*NN*TOTP + NN*TOTP) ? 1 : 0;

    // phase 1: conv over obs[0]
    conv_k<<<dim3(LL, NN), HH>>>(obs, conv_w, conv_b);
    // phase 2: gru0 layer 0
    gemm2_k<<<dim3(LL*NN/128, 3), 256, GEMM_SMEM>>>(pX, g0wih, g0bih, pGi, LL*NN);
    recur2_k<<<NN/2, 384, REC_SMEM>>>(pGi, g0whh, g0bhh, nullptr, pX, LL);
    // phase 2: gru0 layer 1
    gemm2_k<<<dim3(LL*NN/128, 3), 256, GEMM_SMEM>>>(pX, g0wih + G3*HH, g0bih + G3, pGi, LL*NN);
    recur2_k<<<NN/2, 384, REC_SMEM>>>(pGi, g0whh + G3*HH, g0bhh + G3, nullptr, pX, LL);
    // phase 3 prep
    gather_k<<<dim3(TT, NN), HH>>>(p0);
    gumbel_k<<<512, 256>>>();
    // phase 3: layer 0
    gemm2_k<<<dim3(TT*NN/128, 3), 256, GEMM_SMEM>>>(pG, g1wih, g1bih, pGi, TT*NN);
    recur2_k<<<NN/2, 384, REC_SMEM>>>(pGi, g1whh, g1bhh, h0, pG, TT);          // H0 series -> g_G
    // phase 3: layer 1
    gemm2_k<<<dim3(TT*NN/128, 3), 256, GEMM_SMEM>>>(pG, g1wih + G3*HH, g1bih + G3, pGi, TT*NN);
    recur2_k<<<NN/2, 384, REC_SMEM>>>(pGi, g1whh + G3*HH, g1bhh + G3, h0 + NN*HH, pH1, TT);
    // heads + pack
    pack_k<<<TT*NN, 64>>>(pG, pH1, acts, p0, loc, scl, crw, crb, aw, ab, out, has_tail);
}